// round 2
// baseline (speedup 1.0000x reference)
#include <cuda_runtime.h>
#include <math.h>

#define B_TOK 2048
#define D_DIM 2048
#define N_EXP 16
#define TOPK  2

// ---------------- scratch (static device globals; no runtime alloc) ----------
__device__ int   d_count[N_EXP];
__device__ int   d_fill[N_EXP];
__device__ int   d_offset[N_EXP + 1];
__device__ int   d_te[B_TOK * TOPK];     // per-token expert ids (top1, top2)
__device__ float d_tw[B_TOK * TOPK];     // per-token gate weights
__device__ int   d_tok[B_TOK * TOPK];    // slot -> token index
__device__ float d_gw[B_TOK * TOPK];     // slot -> gate weight
__device__ float d_imp[N_EXP];           // importance sums
__device__ float d_H[(size_t)B_TOK * TOPK * D_DIM];  // 32 MB hidden buffer

// ---------------- init: zero output region + counters ------------------------
__global__ void k_init(float* out) {
    int i = blockIdx.x * blockDim.x + threadIdx.x;
    if (i < B_TOK * D_DIM) out[i] = 0.0f;
    if (i < N_EXP) { d_count[i] = 0; d_fill[i] = 0; d_imp[i] = 0.0f; }
}

// ---------------- gating: scores, top-2, softmax, importance ----------------
__global__ void k_gate(const float* __restrict__ x,
                       const float* __restrict__ Wg,
                       const float* __restrict__ bg) {
    int b = blockIdx.x;
    const float* xr = x + (size_t)b * D_DIM;

    float acc[N_EXP];
#pragma unroll
    for (int e = 0; e < N_EXP; e++) acc[e] = 0.0f;

    for (int d = threadIdx.x; d < D_DIM; d += blockDim.x) {
        float xv = xr[d];
        const float4* w = (const float4*)(Wg + (size_t)d * N_EXP);
#pragma unroll
        for (int q = 0; q < 4; q++) {
            float4 v = w[q];
            acc[q * 4 + 0] += xv * v.x;
            acc[q * 4 + 1] += xv * v.y;
            acc[q * 4 + 2] += xv * v.z;
            acc[q * 4 + 3] += xv * v.w;
        }
    }
    // warp reduce
#pragma unroll
    for (int e = 0; e < N_EXP; e++)
#pragma unroll
        for (int o = 16; o > 0; o >>= 1)
            acc[e] += __shfl_down_sync(0xffffffffu, acc[e], o);

    __shared__ float sred[4][N_EXP];
    __shared__ float sc[N_EXP];
    int warp = threadIdx.x >> 5, lane = threadIdx.x & 31;
    if (lane == 0) {
#pragma unroll
        for (int e = 0; e < N_EXP; e++) sred[warp][e] = acc[e];
    }
    __syncthreads();
    if (threadIdx.x < N_EXP) {
        float s = sred[0][threadIdx.x] + sred[1][threadIdx.x] +
                  sred[2][threadIdx.x] + sred[3][threadIdx.x] + bg[threadIdx.x];
        sc[threadIdx.x] = s;
    }
    __syncthreads();

    if (threadIdx.x == 0) {
        // top-2 (strict > : first occurrence of max, matching jax top_k tie rule)
        float v1 = -1e30f; int i1 = 0;
#pragma unroll
        for (int e = 0; e < N_EXP; e++) if (sc[e] > v1) { v1 = sc[e]; i1 = e; }
        float v2 = -1e30f; int i2 = 0;
#pragma unroll
        for (int e = 0; e < N_EXP; e++) if (e != i1 && sc[e] > v2) { v2 = sc[e]; i2 = e; }

        // softmax over the top-2
        float p = __expf(v2 - v1);
        float inv2 = 1.0f / (1.0f + p);
        d_te[b * 2 + 0] = i1; d_te[b * 2 + 1] = i2;
        d_tw[b * 2 + 0] = inv2; d_tw[b * 2 + 1] = p * inv2;
        atomicAdd(&d_count[i1], 1);
        atomicAdd(&d_count[i2], 1);

        // full softmax (importance)
        float ssum = 0.0f, pe[N_EXP];
#pragma unroll
        for (int e = 0; e < N_EXP; e++) { pe[e] = expf(sc[e] - v1); ssum += pe[e]; }
        float invs = 1.0f / ssum;
#pragma unroll
        for (int e = 0; e < N_EXP; e++) atomicAdd(&d_imp[e], pe[e] * invs);
    }
}

// ---------------- scan + losses ----------------------------------------------
__global__ void k_scan(float* out, int out_size) {
    if (threadIdx.x != 0 || blockIdx.x != 0) return;
    int off = 0;
    float sum = 0.0f;
    for (int e = 0; e < N_EXP; e++) {
        d_offset[e] = off;
        off += d_count[e];
        sum += (float)d_count[e];
    }
    d_offset[N_EXP] = off;

    float meanl = sum / (float)N_EXP;
    float varl = 0.0f;
    for (int e = 0; e < N_EXP; e++) {
        float dd = (float)d_count[e] - meanl;
        varl += dd * dd;
    }
    varl /= (float)(N_EXP - 1);
    out[out_size - 2] = varl / (float)B_TOK;   // E * (B/E) = B

    float mi = 0.0f;
    for (int e = 0; e < N_EXP; e++) mi += d_imp[e];
    mi /= (float)N_EXP;
    float vi = 0.0f;
    for (int e = 0; e < N_EXP; e++) {
        float dd = d_imp[e] - mi;
        vi += dd * dd;
    }
    vi /= (float)(N_EXP - 1);
    out[out_size - 1] = vi / (mi + 1e-8f);
}

// ---------------- scatter tokens into per-expert slots ------------------------
__global__ void k_scatter() {
    int b = blockIdx.x * blockDim.x + threadIdx.x;
    if (b >= B_TOK) return;
#pragma unroll
    for (int k = 0; k < TOPK; k++) {
        int e = d_te[b * 2 + k];
        int pos = d_offset[e] + atomicAdd(&d_fill[e], 1);
        d_tok[pos] = b;
        d_gw[pos] = d_tw[b * 2 + k];
    }
}

// ---------------- tiled fp32 GEMMs --------------------------------------------
#define BM 128
#define BN 128
#define BK 16
#define TM 8
#define TN 8

// GEMM1: H[slot, :] = relu( x[tok(slot), :] @ W1[e] + b1[e] )
__global__ void __launch_bounds__(256, 2)
k_gemm1(const float* __restrict__ x, const float* __restrict__ W1,
        const float* __restrict__ b1) {
    int e = blockIdx.z;
    int off = d_offset[e];
    int ne = d_offset[e + 1] - off;
    int row0 = blockIdx.y * BM;
    if (row0 >= ne) return;
    int col0 = blockIdx.x * BN;
    const float* Bm = W1 + (size_t)e * D_DIM * D_DIM;

    __shared__ float As[BK][BM];
    __shared__ float Bs[BK][BN];

    int tid = threadIdx.x;
    int tx = tid & 15, ty = tid >> 4;

    float acc[TM][TN];
#pragma unroll
    for (int i = 0; i < TM; i++)
#pragma unroll
        for (int j = 0; j < TN; j++) acc[i][j] = 0.0f;

    const float* arow[2];
#pragma unroll
    for (int q = 0; q < 2; q++) {
        int Q = tid * 2 + q;
        int m = Q >> 2;
        int gr = row0 + m;
        arow[q] = (gr < ne) ? (x + (size_t)d_tok[off + gr] * D_DIM) : (const float*)0;
    }

    for (int k0 = 0; k0 < D_DIM; k0 += BK) {
#pragma unroll
        for (int q = 0; q < 2; q++) {
            int Q = tid * 2 + q;
            int m = Q >> 2, kq = Q & 3;
            float4 v = arow[q] ? *(const float4*)(arow[q] + k0 + kq * 4)
                               : make_float4(0.f, 0.f, 0.f, 0.f);
            As[kq * 4 + 0][m] = v.x; As[kq * 4 + 1][m] = v.y;
            As[kq * 4 + 2][m] = v.z; As[kq * 4 + 3][m] = v.w;
        }
#pragma unroll
        for (int q = 0; q < 2; q++) {
            int Q = tid * 2 + q;
            int kr = Q >> 5, nq = Q & 31;
            *(float4*)&Bs[kr][nq * 4] =
                *(const float4*)(Bm + (size_t)(k0 + kr) * D_DIM + col0 + nq * 4);
        }
        __syncthreads();
#pragma unroll
        for (int kk = 0; kk < BK; kk++) {
            float a[TM], bb[TN];
#pragma unroll
            for (int i = 0; i < TM; i++) a[i] = As[kk][ty * TM + i];
#pragma unroll
            for (int j = 0; j < TN; j++) bb[j] = Bs[kk][tx * TN + j];
#pragma unroll
            for (int i = 0; i < TM; i++)
#pragma unroll
                for (int j = 0; j < TN; j++) acc[i][j] += a[i] * bb[j];
        }
        __syncthreads();
    }

#pragma unroll
    for (int i = 0; i < TM; i++) {
        int gr = row0 + ty * TM + i;
        if (gr >= ne) continue;
        float* hrow = d_H + (size_t)(off + gr) * D_DIM + col0;
#pragma unroll
        for (int j = 0; j < TN; j++) {
            int n = tx * TN + j;
            float v = acc[i][j] + b1[e * D_DIM + col0 + n];
            hrow[n] = v > 0.0f ? v : 0.0f;
        }
    }
}

// GEMM2: out[tok(slot), :] += gw(slot) * ( H[slot, :] @ W2[e] + b2[e] )
__global__ void __launch_bounds__(256, 2)
k_gemm2(const float* __restrict__ W2, const float* __restrict__ b2,
        float* __restrict__ out) {
    int e = blockIdx.z;
    int off = d_offset[e];
    int ne = d_offset[e + 1] - off;
    int row0 = blockIdx.y * BM;
    if (row0 >= ne) return;
    int col0 = blockIdx.x * BN;
    const float* Bm = W2 + (size_t)e * D_DIM * D_DIM;

    __shared__ float As[BK][BM];
    __shared__ float Bs[BK][BN];

    int tid = threadIdx.x;
    int tx = tid & 15, ty = tid >> 4;

    float acc[TM][TN];
#pragma unroll
    for (int i = 0; i < TM; i++)
#pragma unroll
        for (int j = 0; j < TN; j++) acc[i][j] = 0.0f;

    const float* arow[2];
#pragma unroll
    for (int q = 0; q < 2; q++) {
        int Q = tid * 2 + q;
        int m = Q >> 2;
        int gr = row0 + m;
        arow[q] = (gr < ne) ? (d_H + (size_t)(off + gr) * D_DIM) : (const float*)0;
    }

    for (int k0 = 0; k0 < D_DIM; k0 += BK) {
#pragma unroll
        for (int q = 0; q < 2; q++) {
            int Q = tid * 2 + q;
            int m = Q >> 2, kq = Q & 3;
            float4 v = arow[q] ? *(const float4*)(arow[q] + k0 + kq * 4)
                               : make_float4(0.f, 0.f, 0.f, 0.f);
            As[kq * 4 + 0][m] = v.x; As[kq * 4 + 1][m] = v.y;
            As[kq * 4 + 2][m] = v.z; As[kq * 4 + 3][m] = v.w;
        }
#pragma unroll
        for (int q = 0; q < 2; q++) {
            int Q = tid * 2 + q;
            int kr = Q >> 5, nq = Q & 31;
            *(float4*)&Bs[kr][nq * 4] =
                *(const float4*)(Bm + (size_t)(k0 + kr) * D_DIM + col0 + nq * 4);
        }
        __syncthreads();
#pragma unroll
        for (int kk = 0; kk < BK; kk++) {
            float a[TM], bb[TN];
#pragma unroll
            for (int i = 0; i < TM; i++) a[i] = As[kk][ty * TM + i];
#pragma unroll
            for (int j = 0; j < TN; j++) bb[j] = Bs[kk][tx * TN + j];
#pragma unroll
            for (int i = 0; i < TM; i++)
#pragma unroll
                for (int j = 0; j < TN; j++) acc[i][j] += a[i] * bb[j];
        }
        __syncthreads();
    }

#pragma unroll
    for (int i = 0; i < TM; i++) {
        int gr = row0 + ty * TM + i;
        if (gr >= ne) continue;
        int tok = d_tok[off + gr];
        float w = d_gw[off + gr];
        float* orow = out + (size_t)tok * D_DIM + col0;
#pragma unroll
        for (int j = 0; j < TN; j++) {
            int n = tx * TN + j;
            float v = acc[i][j] + b2[e * D_DIM + col0 + n];
            atomicAdd(&orow[n], w * v);
        }
    }
}

// ---------------- launcher ----------------------------------------------------
extern "C" void kernel_launch(void* const* d_in, const int* in_sizes, int n_in,
                              void* d_out, int out_size) {
    const float* x  = (const float*)d_in[0];
    const float* W1 = (const float*)d_in[1];
    const float* b1 = (const float*)d_in[2];
    const float* W2 = (const float*)d_in[3];
    const float* b2 = (const float*)d_in[4];
    const float* Wg = (const float*)d_in[5];
    const float* bg = (const float*)d_in[6];
    float* out = (float*)d_out;

    k_init<<<(B_TOK * D_DIM + 255) / 256, 256>>>(out);
    k_gate<<<B_TOK, 128>>>(x, Wg, bg);
    k_scan<<<1, 32>>>(out, out_size);
    k_scatter<<<(B_TOK + 255) / 256, 256>>>();

    dim3 grid(D_DIM / BN, B_TOK / BM, N_EXP);   // (16, 16, 16); tiles past n_e exit early
    k_gemm1<<<grid, 256>>>(x, W1, b1);
    k_gemm2<<<grid, 256>>>(W2, b2, out);
}

// round 3
// speedup vs baseline: 2.2754x; 2.2754x over previous
#include <cuda_runtime.h>
#include <math.h>
#include <stdint.h>

#define B_TOK 2048
#define D_DIM 2048
#define N_EXP 16
#define TOPK  2

// ---------------- scratch (static device globals; no runtime alloc) ----------
__device__ int   d_count[N_EXP];
__device__ int   d_fill[N_EXP];
__device__ int   d_offset[N_EXP + 1];
__device__ int   d_te[B_TOK * TOPK];
__device__ float d_tw[B_TOK * TOPK];
__device__ int   d_tok[B_TOK * TOPK];
__device__ float d_gw[B_TOK * TOPK];
__device__ float d_imp[N_EXP];
__device__ float d_H[(size_t)B_TOK * TOPK * D_DIM];  // 32 MB hidden buffer

// ---------------- helpers ------------------------------------------------------
__device__ __forceinline__ uint32_t f2tf32(float f) {
    uint32_t u;
    asm("cvt.rna.tf32.f32 %0, %1;" : "=r"(u) : "f"(f));
    return u;
}

__device__ __forceinline__ void mma_tf32(float& c0, float& c1, float& c2, float& c3,
                                         uint32_t a0, uint32_t a1, uint32_t a2, uint32_t a3,
                                         uint32_t b0, uint32_t b1) {
    asm volatile(
        "mma.sync.aligned.m16n8k8.row.col.f32.tf32.tf32.f32 "
        "{%0,%1,%2,%3}, {%4,%5,%6,%7}, {%8,%9}, {%0,%1,%2,%3};"
        : "+f"(c0), "+f"(c1), "+f"(c2), "+f"(c3)
        : "r"(a0), "r"(a1), "r"(a2), "r"(a3), "r"(b0), "r"(b1));
}

// ---------------- init: zero output region + counters ------------------------
__global__ void k_init(float* out) {
    int i = blockIdx.x * blockDim.x + threadIdx.x;
    if (i < B_TOK * D_DIM) out[i] = 0.0f;
    if (i < N_EXP) { d_count[i] = 0; d_fill[i] = 0; d_imp[i] = 0.0f; }
}

// ---------------- gating: scores, top-2, softmax, importance ----------------
__global__ void k_gate(const float* __restrict__ x,
                       const float* __restrict__ Wg,
                       const float* __restrict__ bg) {
    int b = blockIdx.x;
    const float* xr = x + (size_t)b * D_DIM;

    float acc[N_EXP];
#pragma unroll
    for (int e = 0; e < N_EXP; e++) acc[e] = 0.0f;

    for (int d = threadIdx.x; d < D_DIM; d += blockDim.x) {
        float xv = xr[d];
        const float4* w = (const float4*)(Wg + (size_t)d * N_EXP);
#pragma unroll
        for (int q = 0; q < 4; q++) {
            float4 v = w[q];
            acc[q * 4 + 0] += xv * v.x;
            acc[q * 4 + 1] += xv * v.y;
            acc[q * 4 + 2] += xv * v.z;
            acc[q * 4 + 3] += xv * v.w;
        }
    }
#pragma unroll
    for (int e = 0; e < N_EXP; e++)
#pragma unroll
        for (int o = 16; o > 0; o >>= 1)
            acc[e] += __shfl_down_sync(0xffffffffu, acc[e], o);

    __shared__ float sred[4][N_EXP];
    __shared__ float sc[N_EXP];
    int warp = threadIdx.x >> 5, lane = threadIdx.x & 31;
    if (lane == 0) {
#pragma unroll
        for (int e = 0; e < N_EXP; e++) sred[warp][e] = acc[e];
    }
    __syncthreads();
    if (threadIdx.x < N_EXP) {
        float s = sred[0][threadIdx.x] + sred[1][threadIdx.x] +
                  sred[2][threadIdx.x] + sred[3][threadIdx.x] + bg[threadIdx.x];
        sc[threadIdx.x] = s;
    }
    __syncthreads();

    if (threadIdx.x == 0) {
        float v1 = -1e30f; int i1 = 0;
#pragma unroll
        for (int e = 0; e < N_EXP; e++) if (sc[e] > v1) { v1 = sc[e]; i1 = e; }
        float v2 = -1e30f; int i2 = 0;
#pragma unroll
        for (int e = 0; e < N_EXP; e++) if (e != i1 && sc[e] > v2) { v2 = sc[e]; i2 = e; }

        float p = __expf(v2 - v1);
        float inv2 = 1.0f / (1.0f + p);
        d_te[b * 2 + 0] = i1; d_te[b * 2 + 1] = i2;
        d_tw[b * 2 + 0] = inv2; d_tw[b * 2 + 1] = p * inv2;
        atomicAdd(&d_count[i1], 1);
        atomicAdd(&d_count[i2], 1);

        float ssum = 0.0f, pe[N_EXP];
#pragma unroll
        for (int e = 0; e < N_EXP; e++) { pe[e] = expf(sc[e] - v1); ssum += pe[e]; }
        float invs = 1.0f / ssum;
#pragma unroll
        for (int e = 0; e < N_EXP; e++) atomicAdd(&d_imp[e], pe[e] * invs);
    }
}

// ---------------- scan + losses ----------------------------------------------
__global__ void k_scan(float* out, int out_size) {
    if (threadIdx.x != 0 || blockIdx.x != 0) return;
    int off = 0;
    float sum = 0.0f;
    for (int e = 0; e < N_EXP; e++) {
        d_offset[e] = off;
        off += d_count[e];
        sum += (float)d_count[e];
    }
    d_offset[N_EXP] = off;

    float meanl = sum / (float)N_EXP;
    float varl = 0.0f;
    for (int e = 0; e < N_EXP; e++) {
        float dd = (float)d_count[e] - meanl;
        varl += dd * dd;
    }
    varl /= (float)(N_EXP - 1);
    out[out_size - 2] = varl / (float)B_TOK;

    float mi = 0.0f;
    for (int e = 0; e < N_EXP; e++) mi += d_imp[e];
    mi /= (float)N_EXP;
    float vi = 0.0f;
    for (int e = 0; e < N_EXP; e++) {
        float dd = d_imp[e] - mi;
        vi += dd * dd;
    }
    vi /= (float)(N_EXP - 1);
    out[out_size - 1] = vi / (mi + 1e-8f);
}

// ---------------- scatter tokens into per-expert slots ------------------------
__global__ void k_scatter() {
    int b = blockIdx.x * blockDim.x + threadIdx.x;
    if (b >= B_TOK) return;
#pragma unroll
    for (int k = 0; k < TOPK; k++) {
        int e = d_te[b * 2 + k];
        int pos = d_offset[e] + atomicAdd(&d_fill[e], 1);
        d_tok[pos] = b;
        d_gw[pos] = d_tw[b * 2 + k];
    }
}

// ---------------- tensor-core tf32 GEMMs --------------------------------------
// Block tile 128x128x32; 8 warps in 4(m) x 2(n); warp tile 32x64 = 2x8 mma m16n8k8.
#define BM 128
#define BN 128
#define BK 32
#define ASTRIDE 36    // conflict-free: bank = 4*row + col
#define BSTRIDE 132   // conflict-free: bank = 4*k + n

// Shared GEMM mainloop. Epilogue differs; implemented as two kernels.
// A rows are gathered token rows (gemm1: from x via d_tok; gemm2: from d_H
// directly since H is already slot-ordered).

__global__ void __launch_bounds__(256, 2)
k_gemm1(const float* __restrict__ x, const float* __restrict__ W1,
        const float* __restrict__ b1) {
    int e = blockIdx.z;
    int off = d_offset[e];
    int ne = d_offset[e + 1] - off;
    int row0 = blockIdx.y * BM;
    if (row0 >= ne) return;
    int col0 = blockIdx.x * BN;
    const float* Bm = W1 + (size_t)e * D_DIM * D_DIM;

    __shared__ uint32_t As[BM][ASTRIDE];
    __shared__ uint32_t Bs[BK][BSTRIDE];

    int tid = threadIdx.x;
    int lane = tid & 31, wid = tid >> 5;
    int wm = (wid & 3) * 32;
    int wn = (wid >> 2) * 64;

    // per-thread gmem pointers
    int am = tid >> 1;                       // A row within tile (0..127)
    int agr = row0 + am;
    const float4* pA = (const float4*)0;
    if (agr < ne)
        pA = (const float4*)(x + (size_t)d_tok[off + agr] * D_DIM + (tid & 1) * 16);
    const float4* pB = (const float4*)(Bm + (size_t)(tid >> 3) * D_DIM + col0 + (tid & 7) * 16);

    int aso = (tid & 1) * 16;                // A smem col offset (floats)
    int bk  = tid >> 3;                      // B smem row
    int bn  = (tid & 7) * 16;                // B smem col offset

    float acc[2][8][4];
#pragma unroll
    for (int i = 0; i < 2; i++)
#pragma unroll
        for (int j = 0; j < 8; j++)
#pragma unroll
            for (int c = 0; c < 4; c++) acc[i][j][c] = 0.0f;

    float4 rA[4], rB[4];
    // prologue: tile 0 loads
#pragma unroll
    for (int q = 0; q < 4; q++)
        rA[q] = pA ? pA[q] : make_float4(0.f, 0.f, 0.f, 0.f);
#pragma unroll
    for (int q = 0; q < 4; q++) rB[q] = pB[q];

#pragma unroll
    for (int q = 0; q < 4; q++) {
        uint4 v; v.x = f2tf32(rA[q].x); v.y = f2tf32(rA[q].y);
        v.z = f2tf32(rA[q].z); v.w = f2tf32(rA[q].w);
        *(uint4*)&As[am][aso + q * 4] = v;
    }
#pragma unroll
    for (int q = 0; q < 4; q++) {
        uint4 v; v.x = f2tf32(rB[q].x); v.y = f2tf32(rB[q].y);
        v.z = f2tf32(rB[q].z); v.w = f2tf32(rB[q].w);
        *(uint4*)&Bs[bk][bn + q * 4] = v;
    }
    __syncthreads();

    const int NT = D_DIM / BK;  // 64
    for (int t = 0; t < NT; t++) {
        if (t + 1 < NT) {
            int k0 = (t + 1) * BK;
#pragma unroll
            for (int q = 0; q < 4; q++)
                rA[q] = pA ? pA[k0 / 4 + q] : make_float4(0.f, 0.f, 0.f, 0.f);
            const float4* pBk = (const float4*)((const float*)pB + (size_t)k0 * D_DIM);
#pragma unroll
            for (int q = 0; q < 4; q++) rB[q] = pBk[q];
        }

#pragma unroll
        for (int kk = 0; kk < BK; kk += 8) {
            uint32_t a[2][4];
#pragma unroll
            for (int mt = 0; mt < 2; mt++) {
                int r = wm + mt * 16 + (lane >> 2);
                int c = kk + (lane & 3);
                a[mt][0] = As[r][c];
                a[mt][1] = As[r + 8][c];
                a[mt][2] = As[r][c + 4];
                a[mt][3] = As[r + 8][c + 4];
            }
#pragma unroll
            for (int nt = 0; nt < 8; nt++) {
                int n = wn + nt * 8 + (lane >> 2);
                uint32_t b0 = Bs[kk + (lane & 3)][n];
                uint32_t b1v = Bs[kk + (lane & 3) + 4][n];
#pragma unroll
                for (int mt = 0; mt < 2; mt++)
                    mma_tf32(acc[mt][nt][0], acc[mt][nt][1], acc[mt][nt][2], acc[mt][nt][3],
                             a[mt][0], a[mt][1], a[mt][2], a[mt][3], b0, b1v);
            }
        }
        __syncthreads();
        if (t + 1 < NT) {
#pragma unroll
            for (int q = 0; q < 4; q++) {
                uint4 v; v.x = f2tf32(rA[q].x); v.y = f2tf32(rA[q].y);
                v.z = f2tf32(rA[q].z); v.w = f2tf32(rA[q].w);
                *(uint4*)&As[am][aso + q * 4] = v;
            }
#pragma unroll
            for (int q = 0; q < 4; q++) {
                uint4 v; v.x = f2tf32(rB[q].x); v.y = f2tf32(rB[q].y);
                v.z = f2tf32(rB[q].z); v.w = f2tf32(rB[q].w);
                *(uint4*)&Bs[bk][bn + q * 4] = v;
            }
            __syncthreads();
        }
    }

    // epilogue: bias + relu -> d_H (slot-major)
#pragma unroll
    for (int mt = 0; mt < 2; mt++) {
        int r0 = row0 + wm + mt * 16 + (lane >> 2);
        int r1 = r0 + 8;
#pragma unroll
        for (int nt = 0; nt < 8; nt++) {
            int c = col0 + wn + nt * 8 + (lane & 3) * 2;
            float bb0 = b1[e * D_DIM + c];
            float bb1 = b1[e * D_DIM + c + 1];
            if (r0 < ne) {
                float* h = d_H + (size_t)(off + r0) * D_DIM + c;
                float v0 = acc[mt][nt][0] + bb0;
                float v1 = acc[mt][nt][1] + bb1;
                h[0] = v0 > 0.f ? v0 : 0.f;
                h[1] = v1 > 0.f ? v1 : 0.f;
            }
            if (r1 < ne) {
                float* h = d_H + (size_t)(off + r1) * D_DIM + c;
                float v2 = acc[mt][nt][2] + bb0;
                float v3 = acc[mt][nt][3] + bb1;
                h[0] = v2 > 0.f ? v2 : 0.f;
                h[1] = v3 > 0.f ? v3 : 0.f;
            }
        }
    }
}

__global__ void __launch_bounds__(256, 2)
k_gemm2(const float* __restrict__ W2, const float* __restrict__ b2,
        float* __restrict__ out) {
    int e = blockIdx.z;
    int off = d_offset[e];
    int ne = d_offset[e + 1] - off;
    int row0 = blockIdx.y * BM;
    if (row0 >= ne) return;
    int col0 = blockIdx.x * BN;
    const float* Bm = W2 + (size_t)e * D_DIM * D_DIM;

    __shared__ uint32_t As[BM][ASTRIDE];
    __shared__ uint32_t Bs[BK][BSTRIDE];

    int tid = threadIdx.x;
    int lane = tid & 31, wid = tid >> 5;
    int wm = (wid & 3) * 32;
    int wn = (wid >> 2) * 64;

    int am = tid >> 1;
    int agr = row0 + am;
    const float4* pA = (const float4*)0;
    if (agr < ne)
        pA = (const float4*)(d_H + (size_t)(off + agr) * D_DIM + (tid & 1) * 16);
    const float4* pB = (const float4*)(Bm + (size_t)(tid >> 3) * D_DIM + col0 + (tid & 7) * 16);

    int aso = (tid & 1) * 16;
    int bk  = tid >> 3;
    int bn  = (tid & 7) * 16;

    float acc[2][8][4];
#pragma unroll
    for (int i = 0; i < 2; i++)
#pragma unroll
        for (int j = 0; j < 8; j++)
#pragma unroll
            for (int c = 0; c < 4; c++) acc[i][j][c] = 0.0f;

    float4 rA[4], rB[4];
#pragma unroll
    for (int q = 0; q < 4; q++)
        rA[q] = pA ? pA[q] : make_float4(0.f, 0.f, 0.f, 0.f);
#pragma unroll
    for (int q = 0; q < 4; q++) rB[q] = pB[q];

#pragma unroll
    for (int q = 0; q < 4; q++) {
        uint4 v; v.x = f2tf32(rA[q].x); v.y = f2tf32(rA[q].y);
        v.z = f2tf32(rA[q].z); v.w = f2tf32(rA[q].w);
        *(uint4*)&As[am][aso + q * 4] = v;
    }
#pragma unroll
    for (int q = 0; q < 4; q++) {
        uint4 v; v.x = f2tf32(rB[q].x); v.y = f2tf32(rB[q].y);
        v.z = f2tf32(rB[q].z); v.w = f2tf32(rB[q].w);
        *(uint4*)&Bs[bk][bn + q * 4] = v;
    }
    __syncthreads();

    const int NT = D_DIM / BK;
    for (int t = 0; t < NT; t++) {
        if (t + 1 < NT) {
            int k0 = (t + 1) * BK;
#pragma unroll
            for (int q = 0; q < 4; q++)
                rA[q] = pA ? pA[k0 / 4 + q] : make_float4(0.f, 0.f, 0.f, 0.f);
            const float4* pBk = (const float4*)((const float*)pB + (size_t)k0 * D_DIM);
#pragma unroll
            for (int q = 0; q < 4; q++) rB[q] = pBk[q];
        }

#pragma unroll
        for (int kk = 0; kk < BK; kk += 8) {
            uint32_t a[2][4];
#pragma unroll
            for (int mt = 0; mt < 2; mt++) {
                int r = wm + mt * 16 + (lane >> 2);
                int c = kk + (lane & 3);
                a[mt][0] = As[r][c];
                a[mt][1] = As[r + 8][c];
                a[mt][2] = As[r][c + 4];
                a[mt][3] = As[r + 8][c + 4];
            }
#pragma unroll
            for (int nt = 0; nt < 8; nt++) {
                int n = wn + nt * 8 + (lane >> 2);
                uint32_t b0 = Bs[kk + (lane & 3)][n];
                uint32_t b1v = Bs[kk + (lane & 3) + 4][n];
#pragma unroll
                for (int mt = 0; mt < 2; mt++)
                    mma_tf32(acc[mt][nt][0], acc[mt][nt][1], acc[mt][nt][2], acc[mt][nt][3],
                             a[mt][0], a[mt][1], a[mt][2], a[mt][3], b0, b1v);
            }
        }
        __syncthreads();
        if (t + 1 < NT) {
#pragma unroll
            for (int q = 0; q < 4; q++) {
                uint4 v; v.x = f2tf32(rA[q].x); v.y = f2tf32(rA[q].y);
                v.z = f2tf32(rA[q].z); v.w = f2tf32(rA[q].w);
                *(uint4*)&As[am][aso + q * 4] = v;
            }
#pragma unroll
            for (int q = 0; q < 4; q++) {
                uint4 v; v.x = f2tf32(rB[q].x); v.y = f2tf32(rB[q].y);
                v.z = f2tf32(rB[q].z); v.w = f2tf32(rB[q].w);
                *(uint4*)&Bs[bk][bn + q * 4] = v;
            }
            __syncthreads();
        }
    }

    // epilogue: bias, gate-weight, atomic scatter-add into out
#pragma unroll
    for (int mt = 0; mt < 2; mt++) {
        int r0 = row0 + wm + mt * 16 + (lane >> 2);
        int r1 = r0 + 8;
        int tok0 = (r0 < ne) ? d_tok[off + r0] : 0;
        int tok1 = (r1 < ne) ? d_tok[off + r1] : 0;
        float w0 = (r0 < ne) ? d_gw[off + r0] : 0.f;
        float w1 = (r1 < ne) ? d_gw[off + r1] : 0.f;
#pragma unroll
        for (int nt = 0; nt < 8; nt++) {
            int c = col0 + wn + nt * 8 + (lane & 3) * 2;
            float bb0 = b2[e * D_DIM + c];
            float bb1 = b2[e * D_DIM + c + 1];
            if (r0 < ne) {
                float* o = out + (size_t)tok0 * D_DIM + c;
                atomicAdd(&o[0], w0 * (acc[mt][nt][0] + bb0));
                atomicAdd(&o[1], w0 * (acc[mt][nt][1] + bb1));
            }
            if (r1 < ne) {
                float* o = out + (size_t)tok1 * D_DIM + c;
                atomicAdd(&o[0], w1 * (acc[mt][nt][2] + bb0));
                atomicAdd(&o[1], w1 * (acc[mt][nt][3] + bb1));
            }
        }
    }
}

// ---------------- launcher ----------------------------------------------------
extern "C" void kernel_launch(void* const* d_in, const int* in_sizes, int n_in,
                              void* d_out, int out_size) {
    const float* x  = (const float*)d_in[0];
    const float* W1 = (const float*)d_in[1];
    const float* b1 = (const float*)d_in[2];
    const float* W2 = (const float*)d_in[3];
    const float* b2 = (const float*)d_in[4];
    const float* Wg = (const float*)d_in[5];
    const float* bg = (const float*)d_in[6];
    float* out = (float*)d_out;

    k_init<<<(B_TOK * D_DIM + 255) / 256, 256>>>(out);
    k_gate<<<B_TOK, 128>>>(x, Wg, bg);
    k_scan<<<1, 32>>>(out, out_size);
    k_scatter<<<(B_TOK + 255) / 256, 256>>>();

    dim3 grid(D_DIM / BN, B_TOK / BM, N_EXP);   // (16, 16, 16); ne<=2048 so y=16 covers all
    k_gemm1<<<grid, 256>>>(x, W1, b1);
    k_gemm2<<<grid, 256>>>(W2, b2, out);
}

// round 4
// speedup vs baseline: 2.2828x; 1.0032x over previous
#include <cuda_runtime.h>
#include <math.h>
#include <stdint.h>

#define B_TOK 2048
#define D_DIM 2048
#define N_EXP 16
#define TOPK  2

// ---------------- scratch (static device globals; no runtime alloc) ----------
__device__ int   d_count[N_EXP];
__device__ int   d_fill[N_EXP];
__device__ int   d_offset[N_EXP + 1];
__device__ int   d_te[B_TOK * TOPK];
__device__ float d_tw[B_TOK * TOPK];
__device__ int   d_tok[B_TOK * TOPK];
__device__ float d_gw[B_TOK * TOPK];
__device__ float d_imp[N_EXP];
__device__ float d_H[(size_t)B_TOK * TOPK * D_DIM];  // 32 MB hidden buffer

// ---------------- helpers ------------------------------------------------------
__device__ __forceinline__ uint32_t f2tf32(float f) {
    uint32_t u;
    asm("cvt.rna.tf32.f32 %0, %1;" : "=r"(u) : "f"(f));
    return u;
}

__device__ __forceinline__ void mma_tf32(float& c0, float& c1, float& c2, float& c3,
                                         uint32_t a0, uint32_t a1, uint32_t a2, uint32_t a3,
                                         uint32_t b0, uint32_t b1) {
    asm volatile(
        "mma.sync.aligned.m16n8k8.row.col.f32.tf32.tf32.f32 "
        "{%0,%1,%2,%3}, {%4,%5,%6,%7}, {%8,%9}, {%0,%1,%2,%3};"
        : "+f"(c0), "+f"(c1), "+f"(c2), "+f"(c3)
        : "r"(a0), "r"(a1), "r"(a2), "r"(a3), "r"(b0), "r"(b1));
}

// ---------------- init: zero output region + counters ------------------------
__global__ void k_init(float* out) {
    int i = blockIdx.x * blockDim.x + threadIdx.x;
    if (i < B_TOK * D_DIM) out[i] = 0.0f;
    if (i < N_EXP) { d_count[i] = 0; d_fill[i] = 0; d_imp[i] = 0.0f; }
}

// ---------------- gating: scores, top-2, softmax, importance ----------------
__global__ void k_gate(const float* __restrict__ x,
                       const float* __restrict__ Wg,
                       const float* __restrict__ bg) {
    int b = blockIdx.x;
    const float* xr = x + (size_t)b * D_DIM;

    float acc[N_EXP];
#pragma unroll
    for (int e = 0; e < N_EXP; e++) acc[e] = 0.0f;

    for (int d = threadIdx.x; d < D_DIM; d += blockDim.x) {
        float xv = xr[d];
        const float4* w = (const float4*)(Wg + (size_t)d * N_EXP);
#pragma unroll
        for (int q = 0; q < 4; q++) {
            float4 v = w[q];
            acc[q * 4 + 0] += xv * v.x;
            acc[q * 4 + 1] += xv * v.y;
            acc[q * 4 + 2] += xv * v.z;
            acc[q * 4 + 3] += xv * v.w;
        }
    }
#pragma unroll
    for (int e = 0; e < N_EXP; e++)
#pragma unroll
        for (int o = 16; o > 0; o >>= 1)
            acc[e] += __shfl_down_sync(0xffffffffu, acc[e], o);

    __shared__ float sred[4][N_EXP];
    __shared__ float sc[N_EXP];
    int warp = threadIdx.x >> 5, lane = threadIdx.x & 31;
    if (lane == 0) {
#pragma unroll
        for (int e = 0; e < N_EXP; e++) sred[warp][e] = acc[e];
    }
    __syncthreads();
    if (threadIdx.x < N_EXP) {
        float s = sred[0][threadIdx.x] + sred[1][threadIdx.x] +
                  sred[2][threadIdx.x] + sred[3][threadIdx.x] + bg[threadIdx.x];
        sc[threadIdx.x] = s;
    }
    __syncthreads();

    if (threadIdx.x == 0) {
        float v1 = -1e30f; int i1 = 0;
#pragma unroll
        for (int e = 0; e < N_EXP; e++) if (sc[e] > v1) { v1 = sc[e]; i1 = e; }
        float v2 = -1e30f; int i2 = 0;
#pragma unroll
        for (int e = 0; e < N_EXP; e++) if (e != i1 && sc[e] > v2) { v2 = sc[e]; i2 = e; }

        float p = __expf(v2 - v1);
        float inv2 = 1.0f / (1.0f + p);
        d_te[b * 2 + 0] = i1; d_te[b * 2 + 1] = i2;
        d_tw[b * 2 + 0] = inv2; d_tw[b * 2 + 1] = p * inv2;
        atomicAdd(&d_count[i1], 1);
        atomicAdd(&d_count[i2], 1);

        float ssum = 0.0f, pe[N_EXP];
#pragma unroll
        for (int e = 0; e < N_EXP; e++) { pe[e] = expf(sc[e] - v1); ssum += pe[e]; }
        float invs = 1.0f / ssum;
#pragma unroll
        for (int e = 0; e < N_EXP; e++) atomicAdd(&d_imp[e], pe[e] * invs);
    }
}

// ---------------- scan + losses ----------------------------------------------
__global__ void k_scan(float* out, int out_size) {
    if (threadIdx.x != 0 || blockIdx.x != 0) return;
    int off = 0;
    float sum = 0.0f;
    for (int e = 0; e < N_EXP; e++) {
        d_offset[e] = off;
        off += d_count[e];
        sum += (float)d_count[e];
    }
    d_offset[N_EXP] = off;

    float meanl = sum / (float)N_EXP;
    float varl = 0.0f;
    for (int e = 0; e < N_EXP; e++) {
        float dd = (float)d_count[e] - meanl;
        varl += dd * dd;
    }
    varl /= (float)(N_EXP - 1);
    out[out_size - 2] = varl / (float)B_TOK;

    float mi = 0.0f;
    for (int e = 0; e < N_EXP; e++) mi += d_imp[e];
    mi /= (float)N_EXP;
    float vi = 0.0f;
    for (int e = 0; e < N_EXP; e++) {
        float dd = d_imp[e] - mi;
        vi += dd * dd;
    }
    vi /= (float)(N_EXP - 1);
    out[out_size - 1] = vi / (mi + 1e-8f);
}

// ---------------- scatter tokens into per-expert slots ------------------------
__global__ void k_scatter() {
    int b = blockIdx.x * blockDim.x + threadIdx.x;
    if (b >= B_TOK) return;
#pragma unroll
    for (int k = 0; k < TOPK; k++) {
        int e = d_te[b * 2 + k];
        int pos = d_offset[e] + atomicAdd(&d_fill[e], 1);
        d_tok[pos] = b;
        d_gw[pos] = d_tw[b * 2 + k];
    }
}

// ---------------- tensor-core tf32 GEMMs --------------------------------------
// Block tile 128x128x32; 8 warps in 4(m) x 2(n); warp tile 32x64 = 2x8 mma m16n8k8.
#define BM 128
#define BN 128
#define BK 32
#define ASTRIDE 36    // conflict-free: bank = 4*row + col
#define BSTRIDE 132   // conflict-free: bank = 4*k + n

// Shared GEMM mainloop. Epilogue differs; implemented as two kernels.
// A rows are gathered token rows (gemm1: from x via d_tok; gemm2: from d_H
// directly since H is already slot-ordered).

__global__ void __launch_bounds__(256, 2)
k_gemm1(const float* __restrict__ x, const float* __restrict__ W1,
        const float* __restrict__ b1) {
    int e = blockIdx.z;
    int off = d_offset[e];
    int ne = d_offset[e + 1] - off;
    int row0 = blockIdx.y * BM;
    if (row0 >= ne) return;
    int col0 = blockIdx.x * BN;
    const float* Bm = W1 + (size_t)e * D_DIM * D_DIM;

    __shared__ uint32_t As[BM][ASTRIDE];
    __shared__ uint32_t Bs[BK][BSTRIDE];

    int tid = threadIdx.x;
    int lane = tid & 31, wid = tid >> 5;
    int wm = (wid & 3) * 32;
    int wn = (wid >> 2) * 64;

    // per-thread gmem pointers
    int am = tid >> 1;                       // A row within tile (0..127)
    int agr = row0 + am;
    const float4* pA = (const float4*)0;
    if (agr < ne)
        pA = (const float4*)(x + (size_t)d_tok[off + agr] * D_DIM + (tid & 1) * 16);
    const float4* pB = (const float4*)(Bm + (size_t)(tid >> 3) * D_DIM + col0 + (tid & 7) * 16);

    int aso = (tid & 1) * 16;                // A smem col offset (floats)
    int bk  = tid >> 3;                      // B smem row
    int bn  = (tid & 7) * 16;                // B smem col offset

    float acc[2][8][4];
#pragma unroll
    for (int i = 0; i < 2; i++)
#pragma unroll
        for (int j = 0; j < 8; j++)
#pragma unroll
            for (int c = 0; c < 4; c++) acc[i][j][c] = 0.0f;

    float4 rA[4], rB[4];
    // prologue: tile 0 loads
#pragma unroll
    for (int q = 0; q < 4; q++)
        rA[q] = pA ? pA[q] : make_float4(0.f, 0.f, 0.f, 0.f);
#pragma unroll
    for (int q = 0; q < 4; q++) rB[q] = pB[q];

#pragma unroll
    for (int q = 0; q < 4; q++) {
        uint4 v; v.x = f2tf32(rA[q].x); v.y = f2tf32(rA[q].y);
        v.z = f2tf32(rA[q].z); v.w = f2tf32(rA[q].w);
        *(uint4*)&As[am][aso + q * 4] = v;
    }
#pragma unroll
    for (int q = 0; q < 4; q++) {
        uint4 v; v.x = f2tf32(rB[q].x); v.y = f2tf32(rB[q].y);
        v.z = f2tf32(rB[q].z); v.w = f2tf32(rB[q].w);
        *(uint4*)&Bs[bk][bn + q * 4] = v;
    }
    __syncthreads();

    const int NT = D_DIM / BK;  // 64
    for (int t = 0; t < NT; t++) {
        if (t + 1 < NT) {
            int k0 = (t + 1) * BK;
#pragma unroll
            for (int q = 0; q < 4; q++)
                rA[q] = pA ? pA[k0 / 4 + q] : make_float4(0.f, 0.f, 0.f, 0.f);
            const float4* pBk = (const float4*)((const float*)pB + (size_t)k0 * D_DIM);
#pragma unroll
            for (int q = 0; q < 4; q++) rB[q] = pBk[q];
        }

#pragma unroll
        for (int kk = 0; kk < BK; kk += 8) {
            uint32_t a[2][4];
#pragma unroll
            for (int mt = 0; mt < 2; mt++) {
                int r = wm + mt * 16 + (lane >> 2);
                int c = kk + (lane & 3);
                a[mt][0] = As[r][c];
                a[mt][1] = As[r + 8][c];
                a[mt][2] = As[r][c + 4];
                a[mt][3] = As[r + 8][c + 4];
            }
#pragma unroll
            for (int nt = 0; nt < 8; nt++) {
                int n = wn + nt * 8 + (lane >> 2);
                uint32_t b0 = Bs[kk + (lane & 3)][n];
                uint32_t b1v = Bs[kk + (lane & 3) + 4][n];
#pragma unroll
                for (int mt = 0; mt < 2; mt++)
                    mma_tf32(acc[mt][nt][0], acc[mt][nt][1], acc[mt][nt][2], acc[mt][nt][3],
                             a[mt][0], a[mt][1], a[mt][2], a[mt][3], b0, b1v);
            }
        }
        __syncthreads();
        if (t + 1 < NT) {
#pragma unroll
            for (int q = 0; q < 4; q++) {
                uint4 v; v.x = f2tf32(rA[q].x); v.y = f2tf32(rA[q].y);
                v.z = f2tf32(rA[q].z); v.w = f2tf32(rA[q].w);
                *(uint4*)&As[am][aso + q * 4] = v;
            }
#pragma unroll
            for (int q = 0; q < 4; q++) {
                uint4 v; v.x = f2tf32(rB[q].x); v.y = f2tf32(rB[q].y);
                v.z = f2tf32(rB[q].z); v.w = f2tf32(rB[q].w);
                *(uint4*)&Bs[bk][bn + q * 4] = v;
            }
            __syncthreads();
        }
    }

    // epilogue: bias + relu -> d_H (slot-major)
#pragma unroll
    for (int mt = 0; mt < 2; mt++) {
        int r0 = row0 + wm + mt * 16 + (lane >> 2);
        int r1 = r0 + 8;
#pragma unroll
        for (int nt = 0; nt < 8; nt++) {
            int c = col0 + wn + nt * 8 + (lane & 3) * 2;
            float bb0 = b1[e * D_DIM + c];
            float bb1 = b1[e * D_DIM + c + 1];
            if (r0 < ne) {
                float* h = d_H + (size_t)(off + r0) * D_DIM + c;
                float v0 = acc[mt][nt][0] + bb0;
                float v1 = acc[mt][nt][1] + bb1;
                h[0] = v0 > 0.f ? v0 : 0.f;
                h[1] = v1 > 0.f ? v1 : 0.f;
            }
            if (r1 < ne) {
                float* h = d_H + (size_t)(off + r1) * D_DIM + c;
                float v2 = acc[mt][nt][2] + bb0;
                float v3 = acc[mt][nt][3] + bb1;
                h[0] = v2 > 0.f ? v2 : 0.f;
                h[1] = v3 > 0.f ? v3 : 0.f;
            }
        }
    }
}

__global__ void __launch_bounds__(256, 2)
k_gemm2(const float* __restrict__ W2, const float* __restrict__ b2,
        float* __restrict__ out) {
    int e = blockIdx.z;
    int off = d_offset[e];
    int ne = d_offset[e + 1] - off;
    int row0 = blockIdx.y * BM;
    if (row0 >= ne) return;
    int col0 = blockIdx.x * BN;
    const float* Bm = W2 + (size_t)e * D_DIM * D_DIM;

    __shared__ uint32_t As[BM][ASTRIDE];
    __shared__ uint32_t Bs[BK][BSTRIDE];

    int tid = threadIdx.x;
    int lane = tid & 31, wid = tid >> 5;
    int wm = (wid & 3) * 32;
    int wn = (wid >> 2) * 64;

    int am = tid >> 1;
    int agr = row0 + am;
    const float4* pA = (const float4*)0;
    if (agr < ne)
        pA = (const float4*)(d_H + (size_t)(off + agr) * D_DIM + (tid & 1) * 16);
    const float4* pB = (const float4*)(Bm + (size_t)(tid >> 3) * D_DIM + col0 + (tid & 7) * 16);

    int aso = (tid & 1) * 16;
    int bk  = tid >> 3;
    int bn  = (tid & 7) * 16;

    float acc[2][8][4];
#pragma unroll
    for (int i = 0; i < 2; i++)
#pragma unroll
        for (int j = 0; j < 8; j++)
#pragma unroll
            for (int c = 0; c < 4; c++) acc[i][j][c] = 0.0f;

    float4 rA[4], rB[4];
#pragma unroll
    for (int q = 0; q < 4; q++)
        rA[q] = pA ? pA[q] : make_float4(0.f, 0.f, 0.f, 0.f);
#pragma unroll
    for (int q = 0; q < 4; q++) rB[q] = pB[q];

#pragma unroll
    for (int q = 0; q < 4; q++) {
        uint4 v; v.x = f2tf32(rA[q].x); v.y = f2tf32(rA[q].y);
        v.z = f2tf32(rA[q].z); v.w = f2tf32(rA[q].w);
        *(uint4*)&As[am][aso + q * 4] = v;
    }
#pragma unroll
    for (int q = 0; q < 4; q++) {
        uint4 v; v.x = f2tf32(rB[q].x); v.y = f2tf32(rB[q].y);
        v.z = f2tf32(rB[q].z); v.w = f2tf32(rB[q].w);
        *(uint4*)&Bs[bk][bn + q * 4] = v;
    }
    __syncthreads();

    const int NT = D_DIM / BK;
    for (int t = 0; t < NT; t++) {
        if (t + 1 < NT) {
            int k0 = (t + 1) * BK;
#pragma unroll
            for (int q = 0; q < 4; q++)
                rA[q] = pA ? pA[k0 / 4 + q] : make_float4(0.f, 0.f, 0.f, 0.f);
            const float4* pBk = (const float4*)((const float*)pB + (size_t)k0 * D_DIM);
#pragma unroll
            for (int q = 0; q < 4; q++) rB[q] = pBk[q];
        }

#pragma unroll
        for (int kk = 0; kk < BK; kk += 8) {
            uint32_t a[2][4];
#pragma unroll
            for (int mt = 0; mt < 2; mt++) {
                int r = wm + mt * 16 + (lane >> 2);
                int c = kk + (lane & 3);
                a[mt][0] = As[r][c];
                a[mt][1] = As[r + 8][c];
                a[mt][2] = As[r][c + 4];
                a[mt][3] = As[r + 8][c + 4];
            }
#pragma unroll
            for (int nt = 0; nt < 8; nt++) {
                int n = wn + nt * 8 + (lane >> 2);
                uint32_t b0 = Bs[kk + (lane & 3)][n];
                uint32_t b1v = Bs[kk + (lane & 3) + 4][n];
#pragma unroll
                for (int mt = 0; mt < 2; mt++)
                    mma_tf32(acc[mt][nt][0], acc[mt][nt][1], acc[mt][nt][2], acc[mt][nt][3],
                             a[mt][0], a[mt][1], a[mt][2], a[mt][3], b0, b1v);
            }
        }
        __syncthreads();
        if (t + 1 < NT) {
#pragma unroll
            for (int q = 0; q < 4; q++) {
                uint4 v; v.x = f2tf32(rA[q].x); v.y = f2tf32(rA[q].y);
                v.z = f2tf32(rA[q].z); v.w = f2tf32(rA[q].w);
                *(uint4*)&As[am][aso + q * 4] = v;
            }
#pragma unroll
            for (int q = 0; q < 4; q++) {
                uint4 v; v.x = f2tf32(rB[q].x); v.y = f2tf32(rB[q].y);
                v.z = f2tf32(rB[q].z); v.w = f2tf32(rB[q].w);
                *(uint4*)&Bs[bk][bn + q * 4] = v;
            }
            __syncthreads();
        }
    }

    // epilogue: bias, gate-weight, atomic scatter-add into out
#pragma unroll
    for (int mt = 0; mt < 2; mt++) {
        int r0 = row0 + wm + mt * 16 + (lane >> 2);
        int r1 = r0 + 8;
        int tok0 = (r0 < ne) ? d_tok[off + r0] : 0;
        int tok1 = (r1 < ne) ? d_tok[off + r1] : 0;
        float w0 = (r0 < ne) ? d_gw[off + r0] : 0.f;
        float w1 = (r1 < ne) ? d_gw[off + r1] : 0.f;
#pragma unroll
        for (int nt = 0; nt < 8; nt++) {
            int c = col0 + wn + nt * 8 + (lane & 3) * 2;
            float bb0 = b2[e * D_DIM + c];
            float bb1 = b2[e * D_DIM + c + 1];
            if (r0 < ne) {
                float* o = out + (size_t)tok0 * D_DIM + c;
                atomicAdd(&o[0], w0 * (acc[mt][nt][0] + bb0));
                atomicAdd(&o[1], w0 * (acc[mt][nt][1] + bb1));
            }
            if (r1 < ne) {
                float* o = out + (size_t)tok1 * D_DIM + c;
                atomicAdd(&o[0], w1 * (acc[mt][nt][2] + bb0));
                atomicAdd(&o[1], w1 * (acc[mt][nt][3] + bb1));
            }
        }
    }
}

// ---------------- launcher ----------------------------------------------------
extern "C" void kernel_launch(void* const* d_in, const int* in_sizes, int n_in,
                              void* d_out, int out_size) {
    const float* x  = (const float*)d_in[0];
    const float* W1 = (const float*)d_in[1];
    const float* b1 = (const float*)d_in[2];
    const float* W2 = (const float*)d_in[3];
    const float* b2 = (const float*)d_in[4];
    const float* Wg = (const float*)d_in[5];
    const float* bg = (const float*)d_in[6];
    float* out = (float*)d_out;

    k_init<<<(B_TOK * D_DIM + 255) / 256, 256>>>(out);
    k_gate<<<B_TOK, 128>>>(x, Wg, bg);
    k_scan<<<1, 32>>>(out, out_size);
    k_scatter<<<(B_TOK + 255) / 256, 256>>>();

    dim3 grid(D_DIM / BN, B_TOK / BM, N_EXP);   // (16, 16, 16); ne<=2048 so y=16 covers all
    k_gemm1<<<grid, 256>>>(x, W1, b1);
    k_gemm2<<<grid, 256>>>(W2, b2, out);
}